// round 6
// baseline (speedup 1.0000x reference)
#include <cuda_runtime.h>
#include <cuda_fp16.h>
#include <cstdint>

#define NB 16
#define NS 512
#define NE 512
#define NH 8
#define ND 64

// Scratch (device globals — no allocation allowed). All fp16 now.
__device__ __half g_Qh[NB*NH*NS*ND];     // (b,h,s,d), pre-scaled by 1/32
__device__ __half g_Kh[NB*NH*NS*ND];
__device__ __half g_Vh[NB*NH*NS*ND];
__device__ __half g_cath[NB*NS*2*NE];    // (b*s, [Qf | attn_out])
__device__ __half g_Woh[NE*2*NE];        // fp16 copy of Wo

__device__ __forceinline__ uint32_t pack_h2(float lo, float hi) {
    __half2 h = __float22half2_rn(make_float2(lo, hi));
    return *(uint32_t*)&h;
}
__device__ __forceinline__ uint32_t smem_u32(const void* p) {
    uint32_t a;
    asm("{ .reg .u64 t; cvta.to.shared.u64 t, %1; cvt.u32.u64 %0, t; }"
        : "=r"(a) : "l"(p));
    return a;
}
// mma.sync m16n8k16 f16 inputs, f32 accum: D = A*B + D
__device__ __forceinline__ void mma_f16(float* c, const uint32_t* a, const uint32_t* b)
{
    asm volatile(
        "mma.sync.aligned.m16n8k16.row.col.f32.f16.f16.f32 "
        "{%0,%1,%2,%3}, {%4,%5,%6,%7}, {%8,%9}, {%0,%1,%2,%3};"
        : "+f"(c[0]), "+f"(c[1]), "+f"(c[2]), "+f"(c[3])
        : "r"(a[0]), "r"(a[1]), "r"(a[2]), "r"(a[3]), "r"(b[0]), "r"(b[1]));
}
__device__ __forceinline__ void ldsm_x4(uint32_t* r, uint32_t a) {
    asm volatile("ldmatrix.sync.aligned.m8n8.x4.shared.b16 {%0,%1,%2,%3}, [%4];"
        : "=r"(r[0]), "=r"(r[1]), "=r"(r[2]), "=r"(r[3]) : "r"(a));
}
__device__ __forceinline__ void ldsm_x4_t(uint32_t* r, uint32_t a) {
    asm volatile("ldmatrix.sync.aligned.m8n8.x4.trans.shared.b16 {%0,%1,%2,%3}, [%4];"
        : "=r"(r[0]), "=r"(r[1]), "=r"(r[2]), "=r"(r[3]) : "r"(a));
}

// ---------------------------------------------------------------------------
// Kernel 0: Wo fp32 -> fp16 (one-shot, 2MB)
// ---------------------------------------------------------------------------
__global__ void wo_cvt_kernel(const float* __restrict__ Wo)
{
    const int i = (blockIdx.x * 256 + threadIdx.x) * 4;
    float4 v = *(const float4*)(Wo + i);
    uint2 u = { pack_h2(v.x, v.y), pack_h2(v.z, v.w) };
    *(uint2*)(g_Woh + i) = u;
}

// ---------------------------------------------------------------------------
// Kernel 1: VQC projection -> fp16 outputs (Q pre-scaled by 1/32).
// ---------------------------------------------------------------------------
__global__ void proj_kernel(
    const float* __restrict__ Xq, const float* __restrict__ Xk, const float* __restrict__ Xv,
    const float* __restrict__ Wq_in, const float* __restrict__ bq_in,
    const float* __restrict__ Wk_in, const float* __restrict__ bk_in,
    const float* __restrict__ Wv_in, const float* __restrict__ bv_in,
    const float* __restrict__ wvq, const float* __restrict__ wvk, const float* __restrict__ wvv,
    const float* __restrict__ Wq_o, const float* __restrict__ bq_o,
    const float* __restrict__ Wk_o, const float* __restrict__ bk_o,
    const float* __restrict__ Wv_o, const float* __restrict__ bv_o)
{
    const int t = blockIdx.y;
    const float *X, *Win, *bin, *wv, *Wout, *bout;
    __half* dst;
    if (t == 0)      { X=Xq; Win=Wq_in; bin=bq_in; wv=wvq; Wout=Wq_o; bout=bq_o; dst=g_Qh; }
    else if (t == 1) { X=Xk; Win=Wk_in; bin=bk_in; wv=wvk; Wout=Wk_o; bout=bk_o; dst=g_Kh; }
    else             { X=Xv; Win=Wv_in; bin=bv_in; wv=wvv; Wout=Wv_o; bout=bv_o; dst=g_Vh; }

    const int lane = threadIdx.x & 31;
    const int m = blockIdx.x * 8 + (threadIdx.x >> 5);
    const float* x = X + (size_t)m * 64;
    const float x0 = x[lane];
    const float x1 = x[lane + 32];

    float c[4];
#pragma unroll
    for (int q = 0; q < 4; q++) {
        float p = x0 * Win[q*64 + lane] + x1 * Win[q*64 + 32 + lane];
#pragma unroll
        for (int off = 16; off; off >>= 1)
            p += __shfl_xor_sync(0xffffffffu, p, off);
        c[q] = __cosf(p + bin[q] + wv[q]);
    }
    const float z0 = c[1]*c[2]*c[3];
    const float z1 = c[0]*c[1];
    const float z2 = z1*c[2];
    const float z3 = z2*c[3];

    const int h  = m & 7;
    const int bs = m >> 3;
    const int b  = bs >> 9;
    const int s  = bs & 511;
    const int d0 = lane * 2;
    const float4 w0 = *(const float4*)(Wout + d0*4);
    const float4 w1 = *(const float4*)(Wout + d0*4 + 4);
    const float o0 = z0*w0.x + z1*w0.y + z2*w0.z + z3*w0.w + bout[d0];
    const float o1 = z0*w1.x + z1*w1.y + z2*w1.z + z3*w1.w + bout[d0+1];
    __half* drow = dst + ((size_t)(b*NH + h) * NS + s) * 64 + d0;
    if (t == 0) {
        *(__half2*)drow = __floats2half2_rn(o0 * 0.03125f, o1 * 0.03125f);
        *(__half2*)(g_cath + (size_t)bs*1024 + h*64 + d0) = __floats2half2_rn(o0, o1);
    } else {
        *(__half2*)drow = __floats2half2_rn(o0, o1);
    }
}

// ---------------------------------------------------------------------------
// Kernel 2: flash attention, fp16 mma + ldmatrix; P stays in registers.
// Block: 128 queries x one (b,h); 8 warps x 16-row strips.
// Smem rows: 72 halves (144B) -> ldmatrix conflict-free.
// ---------------------------------------------------------------------------
struct __align__(16) AtSmem {
    __half Qs[128][72];
    __half Ks[64][72];
    __half Vs[64][72];
};
#define QS_OFF 0
#define KS_OFF (128*144)
#define VS_OFF (128*144 + 64*144)

__global__ void __launch_bounds__(256, 2) attn_kernel()
{
    __shared__ AtSmem smem;
    const uint32_t smb = smem_u32(&smem);
    const int tid  = threadIdx.x;
    const int lane = tid & 31;
    const int wid  = tid >> 5;
    const int g    = lane >> 2;
    const int t    = lane & 3;
    const int rb   = wid * 16;
    const int qt   = blockIdx.x & 3;
    const int bh   = blockIdx.x >> 2;

    const __half* Qg = g_Qh + ((size_t)bh * NS + qt*128) * 64;
    const __half* Kg = g_Kh + (size_t)bh * NS * 64;
    const __half* Vg = g_Vh + (size_t)bh * NS * 64;

    // Q tile raw copy (already scaled fp16)
#pragma unroll
    for (int it = 0; it < 4; it++) {
        const int idx = it * 256 + tid;
        const int r = idx >> 3, c8 = (idx & 7) * 8;
        *(uint4*)&smem.Qs[r][c8] = *(const uint4*)(Qg + (size_t)r * 64 + c8);
    }
    __syncthreads();

    // preload Q fragments (A, m16k16) for all 4 k-steps
    uint32_t aq[4][4];
#pragma unroll
    for (int ks = 0; ks < 4; ks++) {
        const uint32_t addr = smb + QS_OFF
            + (uint32_t)(rb + (lane & 15)) * 144
            + (uint32_t)(ks*16 + (lane >> 4)*8) * 2;
        ldsm_x4(aq[ks], addr);
    }

    float m0 = -1e30f, m1 = -1e30f, l0 = 0.f, l1 = 0.f;
    float oacc[8][4];
#pragma unroll
    for (int d = 0; d < 8; d++)
#pragma unroll
        for (int r = 0; r < 4; r++) oacc[d][r] = 0.f;

    for (int kt = 0; kt < 8; kt++) {
        __syncthreads();
        const __half* Kt = Kg + kt * 64 * 64;
        const __half* Vt = Vg + kt * 64 * 64;
#pragma unroll
        for (int it = 0; it < 2; it++) {
            const int idx = it * 256 + tid;
            const int r = idx >> 3, c8 = (idx & 7) * 8;
            *(uint4*)&smem.Ks[r][c8] = *(const uint4*)(Kt + (size_t)r * 64 + c8);
            *(uint4*)&smem.Vs[r][c8] = *(const uint4*)(Vt + (size_t)r * 64 + c8);
        }
        __syncthreads();

        // ---- S = Q K^T ----
        float sacc[8][4];
#pragma unroll
        for (int nt = 0; nt < 8; nt++)
#pragma unroll
            for (int r = 0; r < 4; r++) sacc[nt][r] = 0.f;
#pragma unroll
        for (int ks = 0; ks < 4; ks++) {
#pragma unroll
            for (int ntp = 0; ntp < 4; ntp++) {
                uint32_t bk[4];
                const uint32_t addr = smb + KS_OFF
                    + (uint32_t)(ntp*16 + (lane >> 4)*8 + (lane & 7)) * 144
                    + (uint32_t)(ks*16 + ((lane >> 3) & 1)*8) * 2;
                ldsm_x4(bk, addr);
                mma_f16(sacc[2*ntp],     aq[ks], bk);
                mma_f16(sacc[2*ntp + 1], aq[ks], bk + 2);
            }
        }

        // ---- online softmax in registers ----
        float mt0 = -1e30f, mt1 = -1e30f;
#pragma unroll
        for (int nt = 0; nt < 8; nt++) {
            mt0 = fmaxf(mt0, fmaxf(sacc[nt][0], sacc[nt][1]));
            mt1 = fmaxf(mt1, fmaxf(sacc[nt][2], sacc[nt][3]));
        }
        mt0 = fmaxf(mt0, __shfl_xor_sync(0xffffffffu, mt0, 1));
        mt0 = fmaxf(mt0, __shfl_xor_sync(0xffffffffu, mt0, 2));
        mt1 = fmaxf(mt1, __shfl_xor_sync(0xffffffffu, mt1, 1));
        mt1 = fmaxf(mt1, __shfl_xor_sync(0xffffffffu, mt1, 2));

        const float nm0 = fmaxf(m0, mt0);
        const float nm1 = fmaxf(m1, mt1);
        const float f0 = __expf(m0 - nm0);
        const float f1 = __expf(m1 - nm1);
        m0 = nm0; m1 = nm1;

        float ls0 = 0.f, ls1 = 0.f;
#pragma unroll
        for (int nt = 0; nt < 8; nt++) {
            sacc[nt][0] = __expf(sacc[nt][0] - nm0);
            sacc[nt][1] = __expf(sacc[nt][1] - nm0);
            sacc[nt][2] = __expf(sacc[nt][2] - nm1);
            sacc[nt][3] = __expf(sacc[nt][3] - nm1);
            ls0 += sacc[nt][0] + sacc[nt][1];
            ls1 += sacc[nt][2] + sacc[nt][3];
        }
        ls0 += __shfl_xor_sync(0xffffffffu, ls0, 1);
        ls0 += __shfl_xor_sync(0xffffffffu, ls0, 2);
        ls1 += __shfl_xor_sync(0xffffffffu, ls1, 1);
        ls1 += __shfl_xor_sync(0xffffffffu, ls1, 2);
        l0 = l0 * f0 + ls0;
        l1 = l1 * f1 + ls1;
#pragma unroll
        for (int d = 0; d < 8; d++) {
            oacc[d][0] *= f0; oacc[d][1] *= f0;
            oacc[d][2] *= f1; oacc[d][3] *= f1;
        }

        // ---- O += P V ; P repacked from C-frag to A-frag in registers ----
#pragma unroll
        for (int ks = 0; ks < 4; ks++) {
            uint32_t ap[4];
            ap[0] = pack_h2(sacc[2*ks][0],     sacc[2*ks][1]);
            ap[1] = pack_h2(sacc[2*ks][2],     sacc[2*ks][3]);
            ap[2] = pack_h2(sacc[2*ks + 1][0], sacc[2*ks + 1][1]);
            ap[3] = pack_h2(sacc[2*ks + 1][2], sacc[2*ks + 1][3]);
#pragma unroll
            for (int dtp = 0; dtp < 4; dtp++) {
                uint32_t bv[4];
                const uint32_t addr = smb + VS_OFF
                    + (uint32_t)(ks*16 + ((lane >> 3) & 1)*8 + (lane & 7)) * 144
                    + (uint32_t)(dtp*16 + (lane >> 4)*8) * 2;
                ldsm_x4_t(bv, addr);
                mma_f16(oacc[2*dtp],     ap, bv);
                mma_f16(oacc[2*dtp + 1], ap, bv + 2);
            }
        }
    }

    // ---- epilogue: normalize, write fp16 to g_cath ----
    const int b = bh >> 3, h = bh & 7;
    const float inv0 = 1.f / l0;
    const float inv1 = 1.f / l1;
    const int q0 = qt*128 + rb + g;
    __half* row0 = g_cath + (size_t)(b*NS + q0)*1024 + 512 + h*64;
    __half* row1 = row0 + 8 * 1024;
#pragma unroll
    for (int dt = 0; dt < 8; dt++) {
        *(__half2*)(row0 + dt*8 + 2*t) = __floats2half2_rn(oacc[dt][0]*inv0, oacc[dt][1]*inv0);
        *(__half2*)(row1 + dt*8 + 2*t) = __floats2half2_rn(oacc[dt][2]*inv1, oacc[dt][3]*inv1);
    }
}

// ---------------------------------------------------------------------------
// Kernel 3: out = cat_h(8192x1024) @ Woh^T + bo via fp16 mma + ldmatrix.
// 128x128 tile, 8 warps (2x4), warp 64x32; K-chunks of 64.
// ---------------------------------------------------------------------------
__global__ void __launch_bounds__(256, 2) outproj_kernel(
    const float* __restrict__ bo, float* __restrict__ out)
{
    __shared__ __align__(16) __half As[128][72];
    __shared__ __align__(16) __half Bs[128][72];
    const uint32_t smA = smem_u32(&As[0][0]);
    const uint32_t smB = smem_u32(&Bs[0][0]);
    const int tid  = threadIdx.x;
    const int lane = tid & 31;
    const int wid  = tid >> 5;
    const int wm   = wid >> 2;
    const int wn   = wid & 3;
    const int g    = lane >> 2;
    const int t    = lane & 3;
    const int m0   = blockIdx.x * 128;
    const int e0   = blockIdx.y * 128;

    float acc[4][4][4];
#pragma unroll
    for (int mf = 0; mf < 4; mf++)
#pragma unroll
        for (int nf = 0; nf < 4; nf++)
#pragma unroll
            for (int r = 0; r < 4; r++) acc[mf][nf][r] = 0.f;

    for (int kt = 0; kt < 16; kt++) {
        __syncthreads();
        const __half* Ak = g_cath + (size_t)m0 * 1024 + kt * 64;
        const __half* Bk = g_Woh  + (size_t)e0 * 1024 + kt * 64;
#pragma unroll
        for (int it = 0; it < 4; it++) {
            const int idx = it * 256 + tid;
            const int r = idx >> 3, c8 = (idx & 7) * 8;
            *(uint4*)&As[r][c8] = *(const uint4*)(Ak + (size_t)r * 1024 + c8);
            *(uint4*)&Bs[r][c8] = *(const uint4*)(Bk + (size_t)r * 1024 + c8);
        }
        __syncthreads();

#pragma unroll
        for (int ks = 0; ks < 4; ks++) {
            uint32_t a[4][4], bfr[2][4];
#pragma unroll
            for (int mf = 0; mf < 4; mf++) {
                const uint32_t addr = smA
                    + (uint32_t)(wm*64 + mf*16 + (lane & 15)) * 144
                    + (uint32_t)(ks*16 + (lane >> 4)*8) * 2;
                ldsm_x4(a[mf], addr);
            }
#pragma unroll
            for (int ntp = 0; ntp < 2; ntp++) {
                const uint32_t addr = smB
                    + (uint32_t)(wn*32 + ntp*16 + (lane >> 4)*8 + (lane & 7)) * 144
                    + (uint32_t)(ks*16 + ((lane >> 3) & 1)*8) * 2;
                ldsm_x4(bfr[ntp], addr);
            }
#pragma unroll
            for (int mf = 0; mf < 4; mf++)
#pragma unroll
                for (int nf = 0; nf < 4; nf++)
                    mma_f16(acc[mf][nf], a[mf], &bfr[nf >> 1][(nf & 1) * 2]);
        }
    }

#pragma unroll
    for (int mf = 0; mf < 4; mf++) {
        const int r0 = m0 + wm * 64 + mf * 16 + g;
#pragma unroll
        for (int nf = 0; nf < 4; nf++) {
            const int cc = e0 + wn * 32 + nf * 8 + 2 * t;
            const float b0 = bo[cc], b1 = bo[cc + 1];
            float2 v0 = { acc[mf][nf][0] + b0, acc[mf][nf][1] + b1 };
            float2 v1 = { acc[mf][nf][2] + b0, acc[mf][nf][3] + b1 };
            *(float2*)(out + (size_t)r0 * 512 + cc)       = v0;
            *(float2*)(out + (size_t)(r0 + 8) * 512 + cc) = v1;
        }
    }
}

// ---------------------------------------------------------------------------
extern "C" void kernel_launch(void* const* d_in, const int* in_sizes, int n_in,
                              void* d_out, int out_size)
{
    const float* query = (const float*)d_in[0];
    const float* key   = (const float*)d_in[1];
    const float* value = (const float*)d_in[2];
    // d_in[3]: mask (int32) — no-op in the reference
    const float* Wq_in = (const float*)d_in[4];
    const float* bq_in = (const float*)d_in[5];
    const float* Wk_in = (const float*)d_in[6];
    const float* bk_in = (const float*)d_in[7];
    const float* Wv_in = (const float*)d_in[8];
    const float* bv_in = (const float*)d_in[9];
    const float* wvq   = (const float*)d_in[10];
    const float* wvk   = (const float*)d_in[11];
    const float* wvv   = (const float*)d_in[12];
    const float* Wq_o  = (const float*)d_in[13];
    const float* bq_o  = (const float*)d_in[14];
    const float* Wk_o  = (const float*)d_in[15];
    const float* bk_o  = (const float*)d_in[16];
    const float* Wv_o  = (const float*)d_in[17];
    const float* bv_o  = (const float*)d_in[18];
    const float* Wo    = (const float*)d_in[19];
    const float* bo    = (const float*)d_in[20];
    float* out = (float*)d_out;

    wo_cvt_kernel<<<512, 256>>>(Wo);
    proj_kernel<<<dim3(8192, 3), 256>>>(query, key, value,
                                        Wq_in, bq_in, Wk_in, bk_in, Wv_in, bv_in,
                                        wvq, wvk, wvv,
                                        Wq_o, bq_o, Wk_o, bk_o, Wv_o, bv_o);
    attn_kernel<<<512, 256>>>();
    outproj_kernel<<<dim3(64, 4), 256>>>(bo, out);
}

// round 7
// speedup vs baseline: 1.2877x; 1.2877x over previous
#include <cuda_runtime.h>
#include <cuda_fp16.h>
#include <cstdint>

#define NB 16
#define NS 512
#define NE 512
#define NH 8
#define ND 64

// Scratch (device globals — no allocation allowed). fp16 intermediates.
__device__ __half g_Qh[NB*NH*NS*ND];     // (b,h,s,d), pre-scaled by 1/32
__device__ __half g_Kh[NB*NH*NS*ND];
__device__ __half g_Vh[NB*NH*NS*ND];
__device__ __half g_cath[NB*NS*2*NE];    // (b*s, [Qf | attn_out])
__device__ __half g_Woh[NE*2*NE];        // fp16 copy of Wo

__device__ __forceinline__ uint32_t pack_h2(float lo, float hi) {
    __half2 h = __float22half2_rn(make_float2(lo, hi));
    return *(uint32_t*)&h;
}
__device__ __forceinline__ uint32_t smem_u32(const void* p) {
    uint32_t a;
    asm("{ .reg .u64 t; cvta.to.shared.u64 t, %1; cvt.u32.u64 %0, t; }"
        : "=r"(a) : "l"(p));
    return a;
}
// mma.sync m16n8k16 f16 inputs, f32 accum: D = A*B + D
__device__ __forceinline__ void mma_f16(float* c, const uint32_t* a, const uint32_t* b)
{
    asm volatile(
        "mma.sync.aligned.m16n8k16.row.col.f32.f16.f16.f32 "
        "{%0,%1,%2,%3}, {%4,%5,%6,%7}, {%8,%9}, {%0,%1,%2,%3};"
        : "+f"(c[0]), "+f"(c[1]), "+f"(c[2]), "+f"(c[3])
        : "r"(a[0]), "r"(a[1]), "r"(a[2]), "r"(a[3]), "r"(b[0]), "r"(b[1]));
}
__device__ __forceinline__ void cp_async16(uint32_t dst, const void* src) {
    asm volatile("cp.async.cg.shared.global [%0], [%1], 16;" :: "r"(dst), "l"(src));
}
#define CP_COMMIT() asm volatile("cp.async.commit_group;" ::: "memory")
#define CP_WAIT1()  asm volatile("cp.async.wait_group 1;" ::: "memory")

// ---------------------------------------------------------------------------
// Kernel 0: Wo fp32 -> fp16 (one-shot, 2MB)
// ---------------------------------------------------------------------------
__global__ void wo_cvt_kernel(const float* __restrict__ Wo)
{
    const int i = (blockIdx.x * 256 + threadIdx.x) * 4;
    float4 v = *(const float4*)(Wo + i);
    uint2 u = { pack_h2(v.x, v.y), pack_h2(v.z, v.w) };
    *(uint2*)(g_Woh + i) = u;
}

// ---------------------------------------------------------------------------
// Kernel 1: VQC projection -> fp16 outputs (Q pre-scaled by exact 1/32).
// ---------------------------------------------------------------------------
__global__ void proj_kernel(
    const float* __restrict__ Xq, const float* __restrict__ Xk, const float* __restrict__ Xv,
    const float* __restrict__ Wq_in, const float* __restrict__ bq_in,
    const float* __restrict__ Wk_in, const float* __restrict__ bk_in,
    const float* __restrict__ Wv_in, const float* __restrict__ bv_in,
    const float* __restrict__ wvq, const float* __restrict__ wvk, const float* __restrict__ wvv,
    const float* __restrict__ Wq_o, const float* __restrict__ bq_o,
    const float* __restrict__ Wk_o, const float* __restrict__ bk_o,
    const float* __restrict__ Wv_o, const float* __restrict__ bv_o)
{
    const int t = blockIdx.y;
    const float *X, *Win, *bin, *wv, *Wout, *bout;
    __half* dst;
    if (t == 0)      { X=Xq; Win=Wq_in; bin=bq_in; wv=wvq; Wout=Wq_o; bout=bq_o; dst=g_Qh; }
    else if (t == 1) { X=Xk; Win=Wk_in; bin=bk_in; wv=wvk; Wout=Wk_o; bout=bk_o; dst=g_Kh; }
    else             { X=Xv; Win=Wv_in; bin=bv_in; wv=wvv; Wout=Wv_o; bout=bv_o; dst=g_Vh; }

    const int lane = threadIdx.x & 31;
    const int m = blockIdx.x * 8 + (threadIdx.x >> 5);
    const float* x = X + (size_t)m * 64;
    const float x0 = x[lane];
    const float x1 = x[lane + 32];

    float c[4];
#pragma unroll
    for (int q = 0; q < 4; q++) {
        float p = x0 * Win[q*64 + lane] + x1 * Win[q*64 + 32 + lane];
#pragma unroll
        for (int off = 16; off; off >>= 1)
            p += __shfl_xor_sync(0xffffffffu, p, off);
        c[q] = __cosf(p + bin[q] + wv[q]);
    }
    const float z0 = c[1]*c[2]*c[3];
    const float z1 = c[0]*c[1];
    const float z2 = z1*c[2];
    const float z3 = z2*c[3];

    const int h  = m & 7;
    const int bs = m >> 3;
    const int b  = bs >> 9;
    const int s  = bs & 511;
    const int d0 = lane * 2;
    const float4 w0 = *(const float4*)(Wout + d0*4);
    const float4 w1 = *(const float4*)(Wout + d0*4 + 4);
    const float o0 = z0*w0.x + z1*w0.y + z2*w0.z + z3*w0.w + bout[d0];
    const float o1 = z0*w1.x + z1*w1.y + z2*w1.z + z3*w1.w + bout[d0+1];
    __half* drow = dst + ((size_t)(b*NH + h) * NS + s) * 64 + d0;
    if (t == 0) {
        *(__half2*)drow = __floats2half2_rn(o0 * 0.03125f, o1 * 0.03125f);
        *(__half2*)(g_cath + (size_t)bs*1024 + h*64 + d0) = __floats2half2_rn(o0, o1);
    } else {
        *(__half2*)drow = __floats2half2_rn(o0, o1);
    }
}

// ---------------------------------------------------------------------------
// Kernel 2: flash attention — R5 inner loop (validated), fp16 gmem inputs.
// Block: 128 queries x one (b,h); 8 warps x 16-row strips.
// Smem word rows [36] (data in words 0..31) -> conflict-free scalar frags.
// ---------------------------------------------------------------------------
struct AtSmem {
    uint32_t Qs[128][36];   // half2(q/32) [q][d-pair]
    uint32_t Ks[64][36];    // half2 K    [key][d-pair]
    uint32_t Vt[64][36];    // half2 V^T  [d][key-pair]
    uint32_t Ps[128][36];   // half2 P    [q][key-pair]
};

extern __shared__ unsigned char dyn_smem[];

__global__ void __launch_bounds__(256, 2) attn_kernel()
{
    AtSmem* sm = (AtSmem*)dyn_smem;
    const int tid  = threadIdx.x;
    const int lane = tid & 31;
    const int wid  = tid >> 5;
    const int g    = lane >> 2;
    const int t    = lane & 3;
    const int rb   = wid * 16;
    const int qt   = blockIdx.x & 3;
    const int bh   = blockIdx.x >> 2;

    const __half* Qg = g_Qh + ((size_t)bh * NS + qt*128) * 64;
    const __half* Kg = g_Kh + (size_t)bh * NS * 64;
    const __half* Vg = g_Vh + (size_t)bh * NS * 64;

    // Q tile raw copy (already scaled fp16): 1024 uint4
#pragma unroll
    for (int it = 0; it < 4; it++) {
        const int idx = it * 256 + tid;
        const int r = idx >> 3, c = idx & 7;
        *(uint4*)&sm->Qs[r][c*4] = *(const uint4*)(Qg + (size_t)r * 64 + c*8);
    }

    float m0 = -1e30f, m1 = -1e30f, l0 = 0.f, l1 = 0.f;
    float oacc[8][4];
#pragma unroll
    for (int d = 0; d < 8; d++)
#pragma unroll
        for (int r = 0; r < 4; r++) oacc[d][r] = 0.f;

    for (int kt = 0; kt < 8; kt++) {
        __syncthreads();
        const __half* Kt = Kg + kt * 64 * 64;
        const __half* Vv = Vg + kt * 64 * 64;
#pragma unroll
        for (int it = 0; it < 2; it++) {
            const int idx = it * 256 + tid;
            const int r = idx >> 3, c = idx & 7;
            *(uint4*)&sm->Ks[r][c*4] = *(const uint4*)(Kt + (size_t)r * 64 + c*8);
            // V transpose scatter: 8 halves of row r (d = c*8..c*8+7)
            uint4 vv = *(const uint4*)(Vv + (size_t)r * 64 + c*8);
            const __half* vh = (const __half*)&vv;
#pragma unroll
            for (int i = 0; i < 8; i++)
                ((__half*)&sm->Vt[c*8 + i][0])[r] = vh[i];
        }
        __syncthreads();

        // ---- S = Q K^T : warp strip 16 x 64, 4 k-steps of 16 ----
        float sacc[8][4];
#pragma unroll
        for (int nt = 0; nt < 8; nt++)
#pragma unroll
            for (int r = 0; r < 4; r++) sacc[nt][r] = 0.f;
#pragma unroll
        for (int ks = 0; ks < 4; ks++) {
            const int k0 = ks * 8;
            uint32_t a[4];
            a[0] = sm->Qs[rb + g    ][k0 + t    ];
            a[1] = sm->Qs[rb + g + 8][k0 + t    ];
            a[2] = sm->Qs[rb + g    ][k0 + t + 4];
            a[3] = sm->Qs[rb + g + 8][k0 + t + 4];
#pragma unroll
            for (int nt = 0; nt < 8; nt++) {
                uint32_t b[2];
                b[0] = sm->Ks[nt*8 + g][k0 + t    ];
                b[1] = sm->Ks[nt*8 + g][k0 + t + 4];
                mma_f16(sacc[nt], a, b);
            }
        }

        // ---- online softmax in registers (rows g and g+8) ----
        float mt0 = -1e30f, mt1 = -1e30f;
#pragma unroll
        for (int nt = 0; nt < 8; nt++) {
            mt0 = fmaxf(mt0, fmaxf(sacc[nt][0], sacc[nt][1]));
            mt1 = fmaxf(mt1, fmaxf(sacc[nt][2], sacc[nt][3]));
        }
        mt0 = fmaxf(mt0, __shfl_xor_sync(0xffffffffu, mt0, 1));
        mt0 = fmaxf(mt0, __shfl_xor_sync(0xffffffffu, mt0, 2));
        mt1 = fmaxf(mt1, __shfl_xor_sync(0xffffffffu, mt1, 1));
        mt1 = fmaxf(mt1, __shfl_xor_sync(0xffffffffu, mt1, 2));

        const float nm0 = fmaxf(m0, mt0);
        const float nm1 = fmaxf(m1, mt1);
        const float f0 = __expf(m0 - nm0);
        const float f1 = __expf(m1 - nm1);
        m0 = nm0; m1 = nm1;

        float ls0 = 0.f, ls1 = 0.f;
#pragma unroll
        for (int nt = 0; nt < 8; nt++) {
            sacc[nt][0] = __expf(sacc[nt][0] - nm0);
            sacc[nt][1] = __expf(sacc[nt][1] - nm0);
            sacc[nt][2] = __expf(sacc[nt][2] - nm1);
            sacc[nt][3] = __expf(sacc[nt][3] - nm1);
            ls0 += sacc[nt][0] + sacc[nt][1];
            ls1 += sacc[nt][2] + sacc[nt][3];
        }
        ls0 += __shfl_xor_sync(0xffffffffu, ls0, 1);
        ls0 += __shfl_xor_sync(0xffffffffu, ls0, 2);
        ls1 += __shfl_xor_sync(0xffffffffu, ls1, 1);
        ls1 += __shfl_xor_sync(0xffffffffu, ls1, 2);
        l0 = l0 * f0 + ls0;
        l1 = l1 * f1 + ls1;
#pragma unroll
        for (int d = 0; d < 8; d++) {
            oacc[d][0] *= f0; oacc[d][1] *= f0;
            oacc[d][2] *= f1; oacc[d][3] *= f1;
        }

        // stage P (warp-private rows) as half2
#pragma unroll
        for (int nt = 0; nt < 8; nt++) {
            sm->Ps[rb + g    ][nt*4 + t] = pack_h2(sacc[nt][0], sacc[nt][1]);
            sm->Ps[rb + g + 8][nt*4 + t] = pack_h2(sacc[nt][2], sacc[nt][3]);
        }
        __syncwarp();

        // ---- O += P V ----
#pragma unroll
        for (int ks = 0; ks < 4; ks++) {
            const int k0 = ks * 8;
            uint32_t a[4];
            a[0] = sm->Ps[rb + g    ][k0 + t    ];
            a[1] = sm->Ps[rb + g + 8][k0 + t    ];
            a[2] = sm->Ps[rb + g    ][k0 + t + 4];
            a[3] = sm->Ps[rb + g + 8][k0 + t + 4];
#pragma unroll
            for (int dt = 0; dt < 8; dt++) {
                uint32_t b[2];
                b[0] = sm->Vt[dt*8 + g][k0 + t    ];
                b[1] = sm->Vt[dt*8 + g][k0 + t + 4];
                mma_f16(oacc[dt], a, b);
            }
        }
        __syncwarp();
    }

    // ---- epilogue: normalize, write fp16 to g_cath ----
    const int b = bh >> 3, h = bh & 7;
    const float inv0 = 1.f / l0;
    const float inv1 = 1.f / l1;
    const int q0 = qt*128 + rb + g;
    __half* row0 = g_cath + (size_t)(b*NS + q0)*1024 + 512 + h*64;
    __half* row1 = row0 + 8 * 1024;
#pragma unroll
    for (int dt = 0; dt < 8; dt++) {
        *(__half2*)(row0 + dt*8 + 2*t) = __floats2half2_rn(oacc[dt][0]*inv0, oacc[dt][1]*inv0);
        *(__half2*)(row1 + dt*8 + 2*t) = __floats2half2_rn(oacc[dt][2]*inv1, oacc[dt][3]*inv1);
    }
}

// ---------------------------------------------------------------------------
// Kernel 3: out = cat_h @ Woh^T + bo. R5 inner loop + fp16 loads +
// cp.async double-buffered pipeline (prefetch kt+1 during MMA of kt).
// Dyn smem: 2 buffers x (A[128][36] + B[128][36]) words = 73.7KB.
// ---------------------------------------------------------------------------
#define OPW (128*36)                 // words per tile
__global__ void __launch_bounds__(256, 2) outproj_kernel(
    const float* __restrict__ bo, float* __restrict__ out)
{
    uint32_t* smw = (uint32_t*)dyn_smem;
    const uint32_t smb = smem_u32(smw);
    const int tid  = threadIdx.x;
    const int lane = tid & 31;
    const int wid  = tid >> 5;
    const int wm   = wid >> 2;
    const int wn   = wid & 3;
    const int g    = lane >> 2;
    const int t    = lane & 3;
    const int m0   = blockIdx.x * 128;
    const int e0   = blockIdx.y * 128;

    const __half* Ag = g_cath + (size_t)m0 * 1024;
    const __half* Bg = g_Woh  + (size_t)e0 * 1024;

    // async-load one K-chunk (64 halves wide) into buffer p
    auto load_tiles = [&](int kt, int p) {
        const uint32_t base = smb + (uint32_t)(p * 2 * OPW) * 4;
        const __half* Ak = Ag + kt * 64;
        const __half* Bk = Bg + kt * 64;
#pragma unroll
        for (int it = 0; it < 4; it++) {
            const int idx = it * 256 + tid;
            const int r = idx >> 3, c = idx & 7;
            cp_async16(base + (uint32_t)(r*36 + c*4) * 4,
                       Ak + (size_t)r * 1024 + c*8);
            cp_async16(base + (uint32_t)(OPW + r*36 + c*4) * 4,
                       Bk + (size_t)r * 1024 + c*8);
        }
    };

    float acc[4][4][4];
#pragma unroll
    for (int mf = 0; mf < 4; mf++)
#pragma unroll
        for (int nf = 0; nf < 4; nf++)
#pragma unroll
            for (int r = 0; r < 4; r++) acc[mf][nf][r] = 0.f;

    load_tiles(0, 0);
    CP_COMMIT();

    for (int kt = 0; kt < 16; kt++) {
        const int p = kt & 1;
        if (kt < 15) load_tiles(kt + 1, p ^ 1);
        CP_COMMIT();
        CP_WAIT1();
        __syncthreads();

        const uint32_t* As = smw + p * 2 * OPW;
        const uint32_t* Bs = As + OPW;
#pragma unroll
        for (int ks = 0; ks < 4; ks++) {
            const int k0 = ks * 8;
            uint32_t a[4][4], b[4][2];
#pragma unroll
            for (int mf = 0; mf < 4; mf++) {
                const int r2 = wm * 64 + mf * 16;
                a[mf][0] = As[(r2 + g    )*36 + k0 + t    ];
                a[mf][1] = As[(r2 + g + 8)*36 + k0 + t    ];
                a[mf][2] = As[(r2 + g    )*36 + k0 + t + 4];
                a[mf][3] = As[(r2 + g + 8)*36 + k0 + t + 4];
            }
#pragma unroll
            for (int nf = 0; nf < 4; nf++) {
                const int nb = wn * 32 + nf * 8;
                b[nf][0] = Bs[(nb + g)*36 + k0 + t    ];
                b[nf][1] = Bs[(nb + g)*36 + k0 + t + 4];
            }
#pragma unroll
            for (int mf = 0; mf < 4; mf++)
#pragma unroll
                for (int nf = 0; nf < 4; nf++)
                    mma_f16(acc[mf][nf], a[mf], b[nf]);
        }
        __syncthreads();   // all reads of buffer p done before it is refilled
    }

#pragma unroll
    for (int mf = 0; mf < 4; mf++) {
        const int r0 = m0 + wm * 64 + mf * 16 + g;
#pragma unroll
        for (int nf = 0; nf < 4; nf++) {
            const int cc = e0 + wn * 32 + nf * 8 + 2 * t;
            const float b0 = bo[cc], b1 = bo[cc + 1];
            float2 v0 = { acc[mf][nf][0] + b0, acc[mf][nf][1] + b1 };
            float2 v1 = { acc[mf][nf][2] + b0, acc[mf][nf][3] + b1 };
            *(float2*)(out + (size_t)r0 * 512 + cc)       = v0;
            *(float2*)(out + (size_t)(r0 + 8) * 512 + cc) = v1;
        }
    }
}

// ---------------------------------------------------------------------------
extern "C" void kernel_launch(void* const* d_in, const int* in_sizes, int n_in,
                              void* d_out, int out_size)
{
    const float* query = (const float*)d_in[0];
    const float* key   = (const float*)d_in[1];
    const float* value = (const float*)d_in[2];
    // d_in[3]: mask (int32) — no-op in the reference
    const float* Wq_in = (const float*)d_in[4];
    const float* bq_in = (const float*)d_in[5];
    const float* Wk_in = (const float*)d_in[6];
    const float* bk_in = (const float*)d_in[7];
    const float* Wv_in = (const float*)d_in[8];
    const float* bv_in = (const float*)d_in[9];
    const float* wvq   = (const float*)d_in[10];
    const float* wvk   = (const float*)d_in[11];
    const float* wvv   = (const float*)d_in[12];
    const float* Wq_o  = (const float*)d_in[13];
    const float* bq_o  = (const float*)d_in[14];
    const float* Wk_o  = (const float*)d_in[15];
    const float* bk_o  = (const float*)d_in[16];
    const float* Wv_o  = (const float*)d_in[17];
    const float* bv_o  = (const float*)d_in[18];
    const float* Wo    = (const float*)d_in[19];
    const float* bo    = (const float*)d_in[20];
    float* out = (float*)d_out;

    cudaFuncSetAttribute(attn_kernel, cudaFuncAttributeMaxDynamicSharedMemorySize,
                         (int)sizeof(AtSmem));
    cudaFuncSetAttribute(outproj_kernel, cudaFuncAttributeMaxDynamicSharedMemorySize,
                         4 * OPW * 4);

    wo_cvt_kernel<<<512, 256>>>(Wo);
    proj_kernel<<<dim3(8192, 3), 256>>>(query, key, value,
                                        Wq_in, bq_in, Wk_in, bk_in, Wv_in, bv_in,
                                        wvq, wvk, wvv,
                                        Wq_o, bq_o, Wk_o, bk_o, Wv_o, bv_o);
    attn_kernel<<<512, 256, sizeof(AtSmem)>>>();
    outproj_kernel<<<dim3(64, 4), 256, 4 * OPW * 4>>>(bo, out);
}

// round 8
// speedup vs baseline: 1.4964x; 1.1621x over previous
#include <cuda_runtime.h>
#include <cuda_fp16.h>
#include <cstdint>

#define NB 16
#define NS 512
#define NE 512
#define NH 8
#define ND 64

// Scratch (device globals — no allocation allowed). fp16 intermediates.
__device__ __half g_Qh[NB*NH*NS*ND];     // (b,h,s,d), pre-scaled by 1/32
__device__ __half g_Kh[NB*NH*NS*ND];
__device__ __half g_Vh[NB*NH*NS*ND];
__device__ __half g_cath[NB*NS*2*NE];    // (b*s, [Qf | attn_out])
__device__ __half g_Woh[NE*2*NE];        // fp16 copy of Wo

__device__ __forceinline__ uint32_t pack_h2(float lo, float hi) {
    __half2 h = __float22half2_rn(make_float2(lo, hi));
    return *(uint32_t*)&h;
}
__device__ __forceinline__ uint32_t smem_u32(const void* p) {
    uint32_t a;
    asm("{ .reg .u64 t; cvta.to.shared.u64 t, %1; cvt.u32.u64 %0, t; }"
        : "=r"(a) : "l"(p));
    return a;
}
__device__ __forceinline__ void mma_f16(float* c, const uint32_t* a, const uint32_t* b)
{
    asm volatile(
        "mma.sync.aligned.m16n8k16.row.col.f32.f16.f16.f32 "
        "{%0,%1,%2,%3}, {%4,%5,%6,%7}, {%8,%9}, {%0,%1,%2,%3};"
        : "+f"(c[0]), "+f"(c[1]), "+f"(c[2]), "+f"(c[3])
        : "r"(a[0]), "r"(a[1]), "r"(a[2]), "r"(a[3]), "r"(b[0]), "r"(b[1]));
}
__device__ __forceinline__ void ldsm_x4_t(uint32_t* r, uint32_t a) {
    asm volatile("ldmatrix.sync.aligned.m8n8.x4.trans.shared.b16 {%0,%1,%2,%3}, [%4];"
        : "=r"(r[0]), "=r"(r[1]), "=r"(r[2]), "=r"(r[3]) : "r"(a));
}
__device__ __forceinline__ void cp_async16(uint32_t dst, const void* src) {
    asm volatile("cp.async.cg.shared.global [%0], [%1], 16;" :: "r"(dst), "l"(src));
}
#define CP_COMMIT() asm volatile("cp.async.commit_group;" ::: "memory")
#define CP_WAIT1()  asm volatile("cp.async.wait_group 1;" ::: "memory")

extern __shared__ unsigned char dyn_smem[];

// ---------------------------------------------------------------------------
// Kernel 0: Wo fp32 -> fp16 (one-shot, 2MB)
// ---------------------------------------------------------------------------
__global__ void wo_cvt_kernel(const float* __restrict__ Wo)
{
    const int i = (blockIdx.x * 256 + threadIdx.x) * 4;
    float4 v = *(const float4*)(Wo + i);
    uint2 u = { pack_h2(v.x, v.y), pack_h2(v.z, v.w) };
    *(uint2*)(g_Woh + i) = u;
}

// ---------------------------------------------------------------------------
// Kernel 1: VQC projection -> fp16 outputs (unchanged, known good).
// ---------------------------------------------------------------------------
__global__ void proj_kernel(
    const float* __restrict__ Xq, const float* __restrict__ Xk, const float* __restrict__ Xv,
    const float* __restrict__ Wq_in, const float* __restrict__ bq_in,
    const float* __restrict__ Wk_in, const float* __restrict__ bk_in,
    const float* __restrict__ Wv_in, const float* __restrict__ bv_in,
    const float* __restrict__ wvq, const float* __restrict__ wvk, const float* __restrict__ wvv,
    const float* __restrict__ Wq_o, const float* __restrict__ bq_o,
    const float* __restrict__ Wk_o, const float* __restrict__ bk_o,
    const float* __restrict__ Wv_o, const float* __restrict__ bv_o)
{
    const int t = blockIdx.y;
    const float *X, *Win, *bin, *wv, *Wout, *bout;
    __half* dst;
    if (t == 0)      { X=Xq; Win=Wq_in; bin=bq_in; wv=wvq; Wout=Wq_o; bout=bq_o; dst=g_Qh; }
    else if (t == 1) { X=Xk; Win=Wk_in; bin=bk_in; wv=wvk; Wout=Wk_o; bout=bk_o; dst=g_Kh; }
    else             { X=Xv; Win=Wv_in; bin=bv_in; wv=wvv; Wout=Wv_o; bout=bv_o; dst=g_Vh; }

    const int lane = threadIdx.x & 31;
    const int m = blockIdx.x * 8 + (threadIdx.x >> 5);
    const float* x = X + (size_t)m * 64;
    const float x0 = x[lane];
    const float x1 = x[lane + 32];

    float c[4];
#pragma unroll
    for (int q = 0; q < 4; q++) {
        float p = x0 * Win[q*64 + lane] + x1 * Win[q*64 + 32 + lane];
#pragma unroll
        for (int off = 16; off; off >>= 1)
            p += __shfl_xor_sync(0xffffffffu, p, off);
        c[q] = __cosf(p + bin[q] + wv[q]);
    }
    const float z0 = c[1]*c[2]*c[3];
    const float z1 = c[0]*c[1];
    const float z2 = z1*c[2];
    const float z3 = z2*c[3];

    const int h  = m & 7;
    const int bs = m >> 3;
    const int b  = bs >> 9;
    const int s  = bs & 511;
    const int d0 = lane * 2;
    const float4 w0 = *(const float4*)(Wout + d0*4);
    const float4 w1 = *(const float4*)(Wout + d0*4 + 4);
    const float o0 = z0*w0.x + z1*w0.y + z2*w0.z + z3*w0.w + bout[d0];
    const float o1 = z0*w1.x + z1*w1.y + z2*w1.z + z3*w1.w + bout[d0+1];
    __half* drow = dst + ((size_t)(b*NH + h) * NS + s) * 64 + d0;
    if (t == 0) {
        *(__half2*)drow = __floats2half2_rn(o0 * 0.03125f, o1 * 0.03125f);
        *(__half2*)(g_cath + (size_t)bs*1024 + h*64 + d0) = __floats2half2_rn(o0, o1);
    } else {
        *(__half2*)drow = __floats2half2_rn(o0, o1);
    }
}

// ---------------------------------------------------------------------------
// Kernel 2: flash attention. QK scalar frags + register softmax (R7-fast),
// PV with direct P repack (no Ps smem) + V ldmatrix.trans (R6-validated),
// cp.async double-buffered K/V tiles.
// Smem (words): Qs[128][36] @0, Ks[2][64][36] @4608, Vs[2][64][36] @9216.
// ---------------------------------------------------------------------------
#define AT_KS 4608
#define AT_VS 9216
#define AT_BUF 2304          // words per 64x36 buffer
#define AT_SMEM_BYTES ((4608 + 4*AT_BUF) * 4)

__global__ void __launch_bounds__(256, 2) attn_kernel()
{
    uint32_t* smw = (uint32_t*)dyn_smem;
    const uint32_t smb = smem_u32(smw);
    const int tid  = threadIdx.x;
    const int lane = tid & 31;
    const int wid  = tid >> 5;
    const int g    = lane >> 2;
    const int t    = lane & 3;
    const int rb   = wid * 16;
    const int qt   = blockIdx.x & 3;
    const int bh   = blockIdx.x >> 2;

    const __half* Qg = g_Qh + ((size_t)bh * NS + qt*128) * 64;
    const __half* Kg = g_Kh + (size_t)bh * NS * 64;
    const __half* Vg = g_Vh + (size_t)bh * NS * 64;

    // Q tile raw copy (already scaled fp16)
#pragma unroll
    for (int it = 0; it < 4; it++) {
        const int idx = it * 256 + tid;
        const int r = idx >> 3, c = idx & 7;
        *(uint4*)&smw[r*36 + c*4] = *(const uint4*)(Qg + (size_t)r * 64 + c*8);
    }

    // kv tile async loader (raw rows for both K and V)
    auto load_kv = [&](int kt, int p) {
        const __half* Kt = Kg + kt * 4096;
        const __half* Vv = Vg + kt * 4096;
        const uint32_t kb = smb + (uint32_t)(AT_KS + p*AT_BUF) * 4;
        const uint32_t vb = smb + (uint32_t)(AT_VS + p*AT_BUF) * 4;
#pragma unroll
        for (int it = 0; it < 2; it++) {
            const int idx = it * 256 + tid;
            const int r = idx >> 3, c = idx & 7;
            cp_async16(kb + (uint32_t)(r*36 + c*4) * 4, Kt + (size_t)r * 64 + c*8);
            cp_async16(vb + (uint32_t)(r*36 + c*4) * 4, Vv + (size_t)r * 64 + c*8);
        }
    };
    load_kv(0, 0);
    CP_COMMIT();
    __syncthreads();

    // hoist Q fragments (constant across kv tiles)
    uint32_t aq[4][4];
#pragma unroll
    for (int ks = 0; ks < 4; ks++) {
        const int k0 = ks * 8;
        aq[ks][0] = smw[(rb + g    )*36 + k0 + t    ];
        aq[ks][1] = smw[(rb + g + 8)*36 + k0 + t    ];
        aq[ks][2] = smw[(rb + g    )*36 + k0 + t + 4];
        aq[ks][3] = smw[(rb + g + 8)*36 + k0 + t + 4];
    }

    float m0 = -1e30f, m1 = -1e30f, l0 = 0.f, l1 = 0.f;
    float oacc[8][4];
#pragma unroll
    for (int d = 0; d < 8; d++)
#pragma unroll
        for (int r = 0; r < 4; r++) oacc[d][r] = 0.f;

    for (int kt = 0; kt < 8; kt++) {
        const int p = kt & 1;
        if (kt < 7) load_kv(kt + 1, p ^ 1);
        CP_COMMIT();
        CP_WAIT1();
        __syncthreads();

        const uint32_t* Ks = smw + AT_KS + p*AT_BUF;

        // ---- S = Q K^T ----
        float sacc[8][4];
#pragma unroll
        for (int nt = 0; nt < 8; nt++)
#pragma unroll
            for (int r = 0; r < 4; r++) sacc[nt][r] = 0.f;
#pragma unroll
        for (int ks = 0; ks < 4; ks++) {
            const int k0 = ks * 8;
#pragma unroll
            for (int nt = 0; nt < 8; nt++) {
                uint32_t b[2];
                b[0] = Ks[(nt*8 + g)*36 + k0 + t    ];
                b[1] = Ks[(nt*8 + g)*36 + k0 + t + 4];
                mma_f16(sacc[nt], aq[ks], b);
            }
        }

        // ---- online softmax in registers ----
        float mt0 = -1e30f, mt1 = -1e30f;
#pragma unroll
        for (int nt = 0; nt < 8; nt++) {
            mt0 = fmaxf(mt0, fmaxf(sacc[nt][0], sacc[nt][1]));
            mt1 = fmaxf(mt1, fmaxf(sacc[nt][2], sacc[nt][3]));
        }
        mt0 = fmaxf(mt0, __shfl_xor_sync(0xffffffffu, mt0, 1));
        mt0 = fmaxf(mt0, __shfl_xor_sync(0xffffffffu, mt0, 2));
        mt1 = fmaxf(mt1, __shfl_xor_sync(0xffffffffu, mt1, 1));
        mt1 = fmaxf(mt1, __shfl_xor_sync(0xffffffffu, mt1, 2));

        const float nm0 = fmaxf(m0, mt0);
        const float nm1 = fmaxf(m1, mt1);
        const float f0 = __expf(m0 - nm0);
        const float f1 = __expf(m1 - nm1);
        m0 = nm0; m1 = nm1;

        float ls0 = 0.f, ls1 = 0.f;
#pragma unroll
        for (int nt = 0; nt < 8; nt++) {
            sacc[nt][0] = __expf(sacc[nt][0] - nm0);
            sacc[nt][1] = __expf(sacc[nt][1] - nm0);
            sacc[nt][2] = __expf(sacc[nt][2] - nm1);
            sacc[nt][3] = __expf(sacc[nt][3] - nm1);
            ls0 += sacc[nt][0] + sacc[nt][1];
            ls1 += sacc[nt][2] + sacc[nt][3];
        }
        ls0 += __shfl_xor_sync(0xffffffffu, ls0, 1);
        ls0 += __shfl_xor_sync(0xffffffffu, ls0, 2);
        ls1 += __shfl_xor_sync(0xffffffffu, ls1, 1);
        ls1 += __shfl_xor_sync(0xffffffffu, ls1, 2);
        l0 = l0 * f0 + ls0;
        l1 = l1 * f1 + ls1;
#pragma unroll
        for (int d = 0; d < 8; d++) {
            oacc[d][0] *= f0; oacc[d][1] *= f0;
            oacc[d][2] *= f1; oacc[d][3] *= f1;
        }

        // ---- O += P V : P repacked C-frag -> A-frag in registers;
        //      V B-frags via ldmatrix.trans on raw V rows (R6-validated) ----
        const uint32_t vbase = smb + (uint32_t)(AT_VS + p*AT_BUF) * 4;
#pragma unroll
        for (int ks = 0; ks < 4; ks++) {
            uint32_t ap[4];
            ap[0] = pack_h2(sacc[2*ks][0],     sacc[2*ks][1]);
            ap[1] = pack_h2(sacc[2*ks][2],     sacc[2*ks][3]);
            ap[2] = pack_h2(sacc[2*ks + 1][0], sacc[2*ks + 1][1]);
            ap[3] = pack_h2(sacc[2*ks + 1][2], sacc[2*ks + 1][3]);
#pragma unroll
            for (int dtp = 0; dtp < 4; dtp++) {
                uint32_t bv[4];
                const uint32_t addr = vbase
                    + (uint32_t)(ks*16 + ((lane >> 3) & 1)*8 + (lane & 7)) * 144
                    + (uint32_t)(dtp*16 + (lane >> 4)*8) * 2;
                ldsm_x4_t(bv, addr);
                mma_f16(oacc[2*dtp],     ap, bv);
                mma_f16(oacc[2*dtp + 1], ap, bv + 2);
            }
        }
        __syncthreads();   // reads of buf p done before kt+1 refills it
    }

    // ---- epilogue: normalize, write fp16 to g_cath ----
    const int b = bh >> 3, h = bh & 7;
    const float inv0 = 1.f / l0;
    const float inv1 = 1.f / l1;
    const int q0 = qt*128 + rb + g;
    __half* row0 = g_cath + (size_t)(b*NS + q0)*1024 + 512 + h*64;
    __half* row1 = row0 + 8 * 1024;
#pragma unroll
    for (int dt = 0; dt < 8; dt++) {
        *(__half2*)(row0 + dt*8 + 2*t) = __floats2half2_rn(oacc[dt][0]*inv0, oacc[dt][1]*inv0);
        *(__half2*)(row1 + dt*8 + 2*t) = __floats2half2_rn(oacc[dt][2]*inv1, oacc[dt][3]*inv1);
    }
}

// ---------------------------------------------------------------------------
// Kernel 3: out = cat_h @ Woh^T + bo. 64x128 tile (grid 512 for occupancy),
// cp.async double-buffered. Warp: wm(2)x wn(4), 32x32 warp tile.
// Smem (words/buffer): A 64x36 @0, B 128x36 @2304; x2 buffers.
// ---------------------------------------------------------------------------
#define OPB 6912                       // words per buffer (A+B)
#define OP_SMEM_BYTES (2 * OPB * 4)
__global__ void __launch_bounds__(256, 3) outproj_kernel(
    const float* __restrict__ bo, float* __restrict__ out)
{
    uint32_t* smw = (uint32_t*)dyn_smem;
    const uint32_t smb = smem_u32(smw);
    const int tid  = threadIdx.x;
    const int lane = tid & 31;
    const int wid  = tid >> 5;
    const int wm   = wid >> 2;      // 0..1 (32 rows each)
    const int wn   = wid & 3;       // 0..3 (32 cols each)
    const int g    = lane >> 2;
    const int t    = lane & 3;
    const int m0   = blockIdx.x * 64;
    const int e0   = blockIdx.y * 128;

    const __half* Ag = g_cath + (size_t)m0 * 1024;
    const __half* Bg = g_Woh  + (size_t)e0 * 1024;

    auto load_tiles = [&](int kt, int p) {
        const uint32_t base = smb + (uint32_t)(p * OPB) * 4;
        const __half* Ak = Ag + kt * 64;
        const __half* Bk = Bg + kt * 64;
        {   // A: 64 rows x 8 16B cols = 512
            const int idx = tid;                     // 0..255: first half
            const int r = idx >> 3, c = idx & 7;
            cp_async16(base + (uint32_t)(r*36 + c*4) * 4, Ak + (size_t)r * 1024 + c*8);
            const int idx2 = 256 + tid;
            const int r2 = idx2 >> 3, c2 = idx2 & 7;
            cp_async16(base + (uint32_t)(r2*36 + c2*4) * 4, Ak + (size_t)r2 * 1024 + c2*8);
        }
#pragma unroll
        for (int it = 0; it < 4; it++) {             // B: 128 x 8 = 1024
            const int idx = it * 256 + tid;
            const int r = idx >> 3, c = idx & 7;
            cp_async16(base + (uint32_t)(2304 + r*36 + c*4) * 4, Bk + (size_t)r * 1024 + c*8);
        }
    };

    float acc[2][4][4];
#pragma unroll
    for (int mf = 0; mf < 2; mf++)
#pragma unroll
        for (int nf = 0; nf < 4; nf++)
#pragma unroll
            for (int r = 0; r < 4; r++) acc[mf][nf][r] = 0.f;

    load_tiles(0, 0);
    CP_COMMIT();

    for (int kt = 0; kt < 16; kt++) {
        const int p = kt & 1;
        if (kt < 15) load_tiles(kt + 1, p ^ 1);
        CP_COMMIT();
        CP_WAIT1();
        __syncthreads();

        const uint32_t* As = smw + p * OPB;
        const uint32_t* Bs = As + 2304;
#pragma unroll
        for (int ks = 0; ks < 4; ks++) {
            const int k0 = ks * 8;
            uint32_t a[2][4], b[4][2];
#pragma unroll
            for (int mf = 0; mf < 2; mf++) {
                const int r2 = wm * 32 + mf * 16;
                a[mf][0] = As[(r2 + g    )*36 + k0 + t    ];
                a[mf][1] = As[(r2 + g + 8)*36 + k0 + t    ];
                a[mf][2] = As[(r2 + g    )*36 + k0 + t + 4];
                a[mf][3] = As[(r2 + g + 8)*36 + k0 + t + 4];
            }
#pragma unroll
            for (int nf = 0; nf < 4; nf++) {
                const int nb = wn * 32 + nf * 8;
                b[nf][0] = Bs[(nb + g)*36 + k0 + t    ];
                b[nf][1] = Bs[(nb + g)*36 + k0 + t + 4];
            }
#pragma unroll
            for (int mf = 0; mf < 2; mf++)
#pragma unroll
                for (int nf = 0; nf < 4; nf++)
                    mma_f16(acc[mf][nf], a[mf], b[nf]);
        }
        __syncthreads();
    }

#pragma unroll
    for (int mf = 0; mf < 2; mf++) {
        const int r0 = m0 + wm * 32 + mf * 16 + g;
#pragma unroll
        for (int nf = 0; nf < 4; nf++) {
            const int cc = e0 + wn * 32 + nf * 8 + 2 * t;
            const float b0 = bo[cc], b1 = bo[cc + 1];
            float2 v0 = { acc[mf][nf][0] + b0, acc[mf][nf][1] + b1 };
            float2 v1 = { acc[mf][nf][2] + b0, acc[mf][nf][3] + b1 };
            *(float2*)(out + (size_t)r0 * 512 + cc)       = v0;
            *(float2*)(out + (size_t)(r0 + 8) * 512 + cc) = v1;
        }
    }
}

// ---------------------------------------------------------------------------
extern "C" void kernel_launch(void* const* d_in, const int* in_sizes, int n_in,
                              void* d_out, int out_size)
{
    const float* query = (const float*)d_in[0];
    const float* key   = (const float*)d_in[1];
    const float* value = (const float*)d_in[2];
    // d_in[3]: mask (int32) — no-op in the reference
    const float* Wq_in = (const float*)d_in[4];
    const float* bq_in = (const float*)d_in[5];
    const float* Wk_in = (const float*)d_in[6];
    const float* bk_in = (const float*)d_in[7];
    const float* Wv_in = (const float*)d_in[8];
    const float* bv_in = (const float*)d_in[9];
    const float* wvq   = (const float*)d_in[10];
    const float* wvk   = (const float*)d_in[11];
    const float* wvv   = (const float*)d_in[12];
    const float* Wq_o  = (const float*)d_in[13];
    const float* bq_o  = (const float*)d_in[14];
    const float* Wk_o  = (const float*)d_in[15];
    const float* bk_o  = (const float*)d_in[16];
    const float* Wv_o  = (const float*)d_in[17];
    const float* bv_o  = (const float*)d_in[18];
    const float* Wo    = (const float*)d_in[19];
    const float* bo    = (const float*)d_in[20];
    float* out = (float*)d_out;

    cudaFuncSetAttribute(attn_kernel, cudaFuncAttributeMaxDynamicSharedMemorySize,
                         AT_SMEM_BYTES);
    cudaFuncSetAttribute(outproj_kernel, cudaFuncAttributeMaxDynamicSharedMemorySize,
                         OP_SMEM_BYTES);

    wo_cvt_kernel<<<512, 256>>>(Wo);
    proj_kernel<<<dim3(8192, 3), 256>>>(query, key, value,
                                        Wq_in, bq_in, Wk_in, bk_in, Wv_in, bv_in,
                                        wvq, wvk, wvv,
                                        Wq_o, bq_o, Wk_o, bk_o, Wv_o, bv_o);
    attn_kernel<<<512, 256, AT_SMEM_BYTES>>>();
    outproj_kernel<<<dim3(128, 4), 256, OP_SMEM_BYTES>>>(bo, out);
}